// round 5
// baseline (speedup 1.0000x reference)
#include <cuda_runtime.h>
#include <cuda_bf16.h>

#define PADDING_IDX 0
#define SMOOTHING   0.1f

// Scratch for per-row partial contributions (N = 4096; padded for safety).
// __device__ global: allocation-free per harness rules.
#define MAX_ROWS 8192
__device__ float g_row_partial[MAX_ROWS];

// One block per row. Computes
//   partial[r] = mask_r * ( -(SMOOTHING/V) * sum_v x[r,v]  -  (1-SMOOTHING) * x[r, target_r] )
// then signals PDL so the dependent final-reduce kernel can ramp up while
// the tail wave of this grid drains.
// NOTE: target is int32 on device (JAX x64-disabled downcasts int64 -> int32).
__global__ void __launch_bounds__(256)
ls_row_kernel(const float* __restrict__ x,
              const int* __restrict__ target,
              int V)
{
    const int r = blockIdx.x;
    const int t = target[r];
    const bool valid = (t != PADDING_IDX) && (t >= 0) && (t < V);

    if (valid) {
        const size_t row_off = (size_t)r * (size_t)V;
        const float4* __restrict__ row4 = reinterpret_cast<const float4*>(x + row_off);
        const int nv4 = V >> 2;    // V = 32000 -> 8000 float4 chunks (16B-aligned rows)

        // Two accumulators: shorter FADD dependency chains, deeper MLP.
        float s0 = 0.0f, s1 = 0.0f;
        int i = threadIdx.x;
        for (; i + 256 < nv4; i += 512) {
            float4 a = row4[i];
            float4 b = row4[i + 256];
            s0 += (a.x + a.y) + (a.z + a.w);
            s1 += (b.x + b.y) + (b.z + b.w);
        }
        for (; i < nv4; i += 256) {
            float4 a = row4[i];
            s0 += (a.x + a.y) + (a.z + a.w);
        }
        float s = s0 + s1;
        for (int j = (nv4 << 2) + threadIdx.x; j < V; j += 256)
            s += x[row_off + j];   // tail (not hit for V=32000)

        #pragma unroll
        for (int o = 16; o > 0; o >>= 1)
            s += __shfl_down_sync(0xffffffffu, s, o);

        __shared__ float sh[8];    // 8 warps
        if ((threadIdx.x & 31) == 0) sh[threadIdx.x >> 5] = s;
        __syncthreads();

        if (threadIdx.x < 32) {
            float v = (threadIdx.x < 8) ? sh[threadIdx.x] : 0.0f;
            #pragma unroll
            for (int o = 4; o > 0; o >>= 1)
                v += __shfl_down_sync(0xffffffffu, v, o);
            if (threadIdx.x == 0) {
                const float g = x[row_off + (size_t)t];   // gather, L2-hot
                g_row_partial[r] = -(SMOOTHING / (float)V) * v - (1.0f - SMOOTHING) * g;
            }
        }
        __syncthreads();   // partial published before the PDL trigger below
    } else {
        if (threadIdx.x == 0) g_row_partial[r] = 0.0f;
        __syncthreads();
    }

    // PDL trigger: release-publishes this block's writes to the dependent grid.
    asm volatile("griddepcontrol.launch_dependents;" ::: "memory");
}

// Deterministic single-block reduction of N row partials -> scalar.
// Launched with programmatic stream serialization: its launch/prolog overlaps
// the row kernel's tail; griddepcontrol.wait blocks until all row blocks
// have executed launch_dependents (i.e. all partials are visible).
__global__ void __launch_bounds__(256)
ls_final_kernel(float* __restrict__ out, int n)
{
    asm volatile("griddepcontrol.wait;" ::: "memory");

    const float4* __restrict__ p4 = reinterpret_cast<const float4*>(g_row_partial);
    const int n4 = n >> 2;     // 4096 -> 1024 float4

    float s = 0.0f;
    for (int i = threadIdx.x; i < n4; i += 256) {      // 4 iters @ n=4096
        float4 v = p4[i];
        s += (v.x + v.y) + (v.z + v.w);
    }
    for (int i = (n4 << 2) + threadIdx.x; i < n; i += 256)
        s += g_row_partial[i];                         // tail (unused for 4096)

    #pragma unroll
    for (int o = 16; o > 0; o >>= 1)
        s += __shfl_down_sync(0xffffffffu, s, o);

    __shared__ float sh[8];
    if ((threadIdx.x & 31) == 0) sh[threadIdx.x >> 5] = s;
    __syncthreads();

    if (threadIdx.x < 32) {
        float v = (threadIdx.x < 8) ? sh[threadIdx.x] : 0.0f;
        #pragma unroll
        for (int o = 4; o > 0; o >>= 1)
            v += __shfl_down_sync(0xffffffffu, v, o);
        if (threadIdx.x == 0) out[0] = v;
    }
}

extern "C" void kernel_launch(void* const* d_in, const int* in_sizes, int n_in,
                              void* d_out, int out_size)
{
    const float* x      = (const float*)d_in[0];
    const int*   target = (const int*)d_in[1];
    float*       out    = (float*)d_out;

    const int N = in_sizes[1];         // 4096 rows
    const int V = in_sizes[0] / N;     // 32000 vocab

    ls_row_kernel<<<N, 256>>>(x, target, V);

    // Final reduce with PDL: may begin launching while ls_row_kernel drains.
    cudaLaunchConfig_t cfg = {};
    cfg.gridDim  = dim3(1, 1, 1);
    cfg.blockDim = dim3(256, 1, 1);
    cfg.dynamicSmemBytes = 0;
    cudaLaunchAttribute attr[1];
    attr[0].id = cudaLaunchAttributeProgrammaticStreamSerialization;
    attr[0].val.programmaticStreamSerializationAllowed = 1;
    cfg.attrs = attr;
    cfg.numAttrs = 1;
    cudaLaunchKernelEx(&cfg, ls_final_kernel, out, N);
}